// round 16
// baseline (speedup 1.0000x reference)
#include <cuda_runtime.h>
#include <math.h>
#include <float.h>
#include <stdint.h>

#define L_    12
#define P_    100
#define B_    1024
#define D_    768
#define LP_   8
#define ROW_  (LP_*D_)   // 6144
#define TOPK  5
#define PP    112        // padded P (7 groups of 16)
#define BT    32         // batch tile (scores)
#define DC    32         // d chunk
#define NCH   (D_/DC)    // 24 chunks
#define KPITCH 34        // even pitch -> conflict-free float2 (bank-pair = p%16)
#define XPITCH 34
#define HALF  (PP*KPITCH + BT*XPITCH)   // 4896 floats per buffer
#define CC    128        // col tile (output)
#define OTHR  512        // out_kernel threads
#define SMEM_OUT (P_*CC*4)   // 51200 bytes: P col-slice only -> 4 blocks/SM

// ---- device scratch (no allocations allowed) ----
__device__ float  g_invK[L_*P_];
__device__ float  g_coef[L_*P_];
__device__ float4 g_wq [L_*B_];    // w0..w3 packed
__device__ int4   g_iq [L_*B_];    // i0..i3 packed
__device__ float  g_wl [L_*B_];    // w4
__device__ int    g_il [L_*B_];    // i4
__device__ int    g_sink;

// =====================================================================
// Kernel A: one warp per (l,p): invK and coef = dot(l2norm(K),l2norm(A))
// =====================================================================
__global__ __launch_bounds__(256) void prep_kernel(const float* __restrict__ K_all,
                                                   const float* __restrict__ A_all) {
    int gw = (blockIdx.x * 256 + threadIdx.x) >> 5;   // 0..1199
    int ln = threadIdx.x & 31;
    if (gw >= L_ * P_) return;
    const float* Kr = K_all + (size_t)gw * D_;
    const float* Ar = A_all + (size_t)gw * D_;
    float kk = 0.f, aa = 0.f, ka = 0.f;
    #pragma unroll
    for (int i = 0; i < 6; ++i) {
        float4 k = *(const float4*)(Kr + ((i << 5) + ln) * 4);
        float4 a = *(const float4*)(Ar + ((i << 5) + ln) * 4);
        kk = fmaf(k.x,k.x, fmaf(k.y,k.y, fmaf(k.z,k.z, fmaf(k.w,k.w, kk))));
        aa = fmaf(a.x,a.x, fmaf(a.y,a.y, fmaf(a.z,a.z, fmaf(a.w,a.w, aa))));
        ka = fmaf(k.x,a.x, fmaf(k.y,a.y, fmaf(k.z,a.z, fmaf(k.w,a.w, ka))));
    }
    #pragma unroll
    for (int o = 16; o; o >>= 1) {
        kk += __shfl_xor_sync(0xffffffffu, kk, o);
        aa += __shfl_xor_sync(0xffffffffu, aa, o);
        ka += __shfl_xor_sync(0xffffffffu, ka, o);
    }
    if (ln == 0) {
        float ik = 1.f / fmaxf(sqrtf(kk), 1e-12f);
        float ia = 1.f / fmaxf(sqrtf(aa), 1e-12f);
        g_invK[gw] = ik;
        g_coef[gw] = ka * ik * ia;
    }
}

// =====================================================================
// Kernel B: scores GEMM (fp32) + top-5.  Block = (l, 32 batches), 128 thr.
// Double-buffered smem staging with register prefetch (R12 win).
// Lane 0 accumulates the 5 (w, idx) in registers and writes PACKED
// float4/int4 outputs.  Unchanged this round.
// =====================================================================
__global__ __launch_bounds__(128) void score_kernel(const float* __restrict__ x_query,
                                                    const float* __restrict__ K_all) {
    const int l  = blockIdx.y;
    const int b0 = blockIdx.x * BT;

    __shared__ __align__(16) float pool[2 * HALF];   // 39.2 KB

    const int t   = threadIdx.x;
    const int tx  = t & 15;          // p group
    const int ty  = t >> 4;          // 0..7 -> batches 4ty..4ty+3
    const int ldp = (t & 7) << 2;    // loader d offset 0..28
    const int lr  = t >> 3;          // loader row 0..15

    float acc[4][7];
    #pragma unroll
    for (int i = 0; i < 4; ++i)
        #pragma unroll
        for (int j = 0; j < 7; ++j) acc[i][j] = 0.f;

    const float* Kb = K_all   + (size_t)l * P_ * D_ + ldp;
    const float* xb = x_query + (size_t)l * D_ + ldp;

    float4 pk[7], px[2];
    #pragma unroll
    for (int j = 0; j < 7; ++j) {
        int p = lr + (j << 4);
        pk[j] = (p < P_) ? *(const float4*)(Kb + (size_t)p * D_)
                         : make_float4(0.f, 0.f, 0.f, 0.f);
    }
    #pragma unroll
    for (int i = 0; i < 2; ++i)
        px[i] = *(const float4*)(xb + (size_t)(b0 + lr + (i << 4)) * (L_ * D_));
    {
        float* Kc = pool;
        float* Xc = pool + PP * KPITCH;
        #pragma unroll
        for (int j = 0; j < 7; ++j) {
            float* r = &Kc[(lr + (j << 4)) * KPITCH + ldp];
            *(float2*)(r    ) = make_float2(pk[j].x, pk[j].y);
            *(float2*)(r + 2) = make_float2(pk[j].z, pk[j].w);
        }
        #pragma unroll
        for (int i = 0; i < 2; ++i) {
            float* r = &Xc[(lr + (i << 4)) * XPITCH + ldp];
            *(float2*)(r    ) = make_float2(px[i].x, px[i].y);
            *(float2*)(r + 2) = make_float2(px[i].z, px[i].w);
        }
    }
    __syncthreads();

    for (int c = 0; c < NCH; ++c) {
        const float* base = pool + (c & 1) * HALF;
        const float* Kc = base;
        const float* Xc = base + PP * KPITCH;

        if (c + 1 < NCH) {
            int d0 = (c + 1) * DC;
            #pragma unroll
            for (int j = 0; j < 7; ++j) {
                int p = lr + (j << 4);
                pk[j] = (p < P_) ? *(const float4*)(Kb + (size_t)p * D_ + d0)
                                 : make_float4(0.f, 0.f, 0.f, 0.f);
            }
            #pragma unroll
            for (int i = 0; i < 2; ++i)
                px[i] = *(const float4*)(xb + (size_t)(b0 + lr + (i << 4)) * (L_ * D_) + d0);
        }

        #pragma unroll 2
        for (int dd = 0; dd < DC; dd += 2) {
            float2 kv[7], xv[4];
            #pragma unroll
            for (int j = 0; j < 7; ++j) kv[j] = *(const float2*)&Kc[(tx + (j << 4)) * KPITCH + dd];
            #pragma unroll
            for (int i = 0; i < 4; ++i) xv[i] = *(const float2*)&Xc[(4 * ty + i) * XPITCH + dd];
            #pragma unroll
            for (int i = 0; i < 4; ++i)
                #pragma unroll
                for (int j = 0; j < 7; ++j) {
                    acc[i][j] = fmaf(xv[i].x, kv[j].x, acc[i][j]);
                    acc[i][j] = fmaf(xv[i].y, kv[j].y, acc[i][j]);
                }
        }

        if (c + 1 < NCH) {
            float* dst = pool + ((c + 1) & 1) * HALF;
            float* Kd = dst;
            float* Xd = dst + PP * KPITCH;
            #pragma unroll
            for (int j = 0; j < 7; ++j) {
                float* r = &Kd[(lr + (j << 4)) * KPITCH + ldp];
                *(float2*)(r    ) = make_float2(pk[j].x, pk[j].y);
                *(float2*)(r + 2) = make_float2(pk[j].z, pk[j].w);
            }
            #pragma unroll
            for (int i = 0; i < 2; ++i) {
                float* r = &Xd[(lr + (i << 4)) * XPITCH + ldp];
                *(float2*)(r    ) = make_float2(px[i].x, px[i].y);
                *(float2*)(r + 2) = make_float2(px[i].z, px[i].w);
            }
        }
        __syncthreads();
    }

    float* S = pool;   // [BT][128], aliases buffer 0

    #pragma unroll
    for (int j = 0; j < 8; ++j) {
        int p = tx + (j << 4);
        float ik = (p < P_) ? g_invK[l * P_ + p] : 0.f;
        #pragma unroll
        for (int i = 0; i < 4; ++i) {
            float v = (j < 7 && p < P_) ? acc[i][j] * ik : -FLT_MAX;
            S[(4 * ty + i) * 128 + p] = v;
        }
    }
    __syncthreads();

    const int w  = t >> 5;
    const int ln = t & 31;
    for (int bi = 0; bi < 8; ++bi) {
        int b = (w << 3) + bi;           // 0..31
        float v[4];
        #pragma unroll
        for (int j = 0; j < 4; ++j) v[j] = S[b * 128 + ln + (j << 5)];
        float wv[TOPK]; int iv[TOPK];
        #pragma unroll
        for (int k = 0; k < TOPK; ++k) {
            float bv = v[0]; int bj = 0;
            #pragma unroll
            for (int j = 1; j < 4; ++j) if (v[j] > bv) { bv = v[j]; bj = j; }
            int bidx = ln + (bj << 5);
            #pragma unroll
            for (int o = 16; o; o >>= 1) {
                float ov = __shfl_xor_sync(0xffffffffu, bv, o);
                int   oi = __shfl_xor_sync(0xffffffffu, bidx, o);
                if (ov > bv || (ov == bv && oi < bidx)) { bv = ov; bidx = oi; }
            }
            wv[k] = g_coef[l * P_ + bidx];   // only lane 0's value is used
            iv[k] = bidx;
            if ((bidx & 31) == ln) v[bidx >> 5] = -FLT_MAX;
        }
        if (ln == 0) {
            int gb = l * B_ + b0 + b;
            g_wq[gb] = make_float4(wv[0], wv[1], wv[2], wv[3]);
            g_iq[gb] = make_int4 (iv[0], iv[1], iv[2], iv[3]);
            g_wl[gb] = wv[4];
            g_il[gb] = iv[4];
        }
    }
}

// =====================================================================
// Kernel C: OUT[l,b,:] = sum_k w[l,b,k] * P_all[l, idx[l,b,k], :]
// Block = (l, coltile 128) serving ALL 1024 batches; P col-slice staged
// once per block.  R16: weights/indices read via broadcast LDG with a
// one-iteration register prefetch (no smem) -> smem 92 KB -> 50 KB ->
// 4 blocks/SM = 64 warps/SM (was 2 blocks / 32 warps, occ 45%).
// =====================================================================
__global__ __launch_bounds__(OTHR) void out_kernel(const float* __restrict__ P_all,
                                                   float* __restrict__ out) {
    extern __shared__ __align__(16) float Ps[];   // [P_][CC], 50 KB

    const int l    = blockIdx.y;
    const int col0 = blockIdx.x * CC;
    const int t    = threadIdx.x;

    // stage P col-slice once: 100 rows x 128 cols (float4 loads/stores)
    const float* Pl = P_all + (size_t)l * P_ * ROW_ + col0;
    for (int i = t; i < P_ * (CC / 4); i += OTHR) {
        int p = i >> 5, c = i & 31;              // 32 float4 per row
        float4 v = *(const float4*)(Pl + (size_t)p * ROW_ + 4 * c);
        *(float4*)&Ps[p * CC + 4 * c] = v;
    }
    __syncthreads();

    const int w  = t >> 5;                       // 0..15
    const int ln = t & 31;
    const int gbase = l * B_;
    float* ob = out + (size_t)l * B_ * ROW_ + col0 + 4 * ln;

    // register prefetch of (w, idx) for the first batch
    float4 wv = g_wq[gbase + w];
    int4   iv = g_iq[gbase + w];
    float  w4 = g_wl[gbase + w];
    int    i4 = g_il[gbase + w];

    for (int b = w; b < B_; b += OTHR / 32) {
        float4 wc = wv; int4 ic = iv; float w4c = w4; int i4c = i4;
        int bn = b + OTHR / 32;
        if (bn < B_) {                           // prefetch next (broadcast LDG)
            wv = g_wq[gbase + bn];
            iv = g_iq[gbase + bn];
            w4 = g_wl[gbase + bn];
            i4 = g_il[gbase + bn];
        }
        float4 p0 = *(const float4*)&Ps[ic.x * CC + 4 * ln];
        float4 p1 = *(const float4*)&Ps[ic.y * CC + 4 * ln];
        float4 p2 = *(const float4*)&Ps[ic.z * CC + 4 * ln];
        float4 p3 = *(const float4*)&Ps[ic.w * CC + 4 * ln];
        float4 p4 = *(const float4*)&Ps[i4c  * CC + 4 * ln];
        float4 o;
        o.x = fmaf(w4c, p4.x, fmaf(wc.w, p3.x, fmaf(wc.z, p2.x, fmaf(wc.y, p1.x, wc.x * p0.x))));
        o.y = fmaf(w4c, p4.y, fmaf(wc.w, p3.y, fmaf(wc.z, p2.y, fmaf(wc.y, p1.y, wc.x * p0.y))));
        o.z = fmaf(w4c, p4.z, fmaf(wc.w, p3.z, fmaf(wc.z, p2.z, fmaf(wc.y, p1.z, wc.x * p0.z))));
        o.w = fmaf(w4c, p4.w, fmaf(wc.w, p3.w, fmaf(wc.z, p2.w, fmaf(wc.y, p1.w, wc.x * p0.w))));
        *(float4*)(ob + (size_t)b * ROW_) = o;
    }
}

// =====================================================================
// Dummy launch at position 3: ncu captures launch position 4 (confirmed
// R9/R11-R15).  Order prep, score, phase, out -> profile lands on the
// NEW out_kernel.
// =====================================================================
__global__ void phase_kernel() { g_sink = 1; }

// =====================================================================
extern "C" void kernel_launch(void* const* d_in, const int* in_sizes, int n_in,
                              void* d_out, int out_size) {
    const float* x_query = (const float*)d_in[0];  // [B, L, D]
    const float* K_all   = (const float*)d_in[1];  // [L, P, D]
    const float* A_all   = (const float*)d_in[2];  // [L, P, D]
    const float* P_all   = (const float*)d_in[3];  // [L, P, Lp, D]
    float* out = (float*)d_out;                    // [L, B, Lp, E]
    (void)in_sizes; (void)n_in; (void)out_size;

    cudaFuncSetAttribute(out_kernel, cudaFuncAttributeMaxDynamicSharedMemorySize, SMEM_OUT);

    prep_kernel<<<(L_ * P_ * 32 + 255) / 256, 256>>>(K_all, A_all);
    score_kernel<<<dim3(B_ / BT, L_), 128>>>(x_query, K_all);
    phase_kernel<<<1, 1>>>();
    out_kernel<<<dim3(ROW_ / CC, L_), OTHR, SMEM_OUT>>>(P_all, out);
}

// round 17
// speedup vs baseline: 1.1663x; 1.1663x over previous
#include <cuda_runtime.h>
#include <math.h>
#include <float.h>
#include <stdint.h>

#define L_    12
#define P_    100
#define B_    1024
#define D_    768
#define LP_   8
#define ROW_  (LP_*D_)   // 6144
#define TOPK  5
#define PP    112        // padded P (7 groups of 16)
#define BT    32         // batch tile (scores)
#define DC    32         // d chunk
#define NCH   (D_/DC)    // 24 chunks
#define KPITCH 34        // even pitch -> conflict-free float2 (bank-pair = p%16)
#define XPITCH 34
#define HALF  (PP*KPITCH + BT*XPITCH)   // 4896 floats per buffer
#define CC    128        // col tile (output)
#define OTHR  512        // out_kernel threads
// dynamic smem layout for out_kernel (bytes): 75 KB -> 3 blocks/SM
#define SM_PS   0                    // P slice: 100*128*4 = 51200
#define SM_WQ   51200                // float4[1024] = 16384
#define SM_AUX  (SM_WQ + 16384)      // uint2[1024]  = 8192  {w4 bits, idx0..3 packed}
#define SM_I4   (SM_AUX + 8192)      // uint8[1024]  = 1024
#define SMEM_OUT (SM_I4 + 1024)      // 76800 bytes = 75 KB

// ---- device scratch (no allocations allowed) ----
__device__ float  g_invK[L_*P_];
__device__ float  g_coef[L_*P_];
__device__ float4 g_wq [L_*B_];           // w0..w3 packed
__device__ uint2  g_aux[L_*B_];           // {w4 bits, idx0..3 packed bytes}
__device__ unsigned char g_i4[L_*B_];     // idx4
__device__ int    g_sink;

// =====================================================================
// Kernel A: one warp per (l,p): invK and coef = dot(l2norm(K),l2norm(A))
// =====================================================================
__global__ __launch_bounds__(256) void prep_kernel(const float* __restrict__ K_all,
                                                   const float* __restrict__ A_all) {
    int gw = (blockIdx.x * 256 + threadIdx.x) >> 5;   // 0..1199
    int ln = threadIdx.x & 31;
    if (gw >= L_ * P_) return;
    const float* Kr = K_all + (size_t)gw * D_;
    const float* Ar = A_all + (size_t)gw * D_;
    float kk = 0.f, aa = 0.f, ka = 0.f;
    #pragma unroll
    for (int i = 0; i < 6; ++i) {
        float4 k = *(const float4*)(Kr + ((i << 5) + ln) * 4);
        float4 a = *(const float4*)(Ar + ((i << 5) + ln) * 4);
        kk = fmaf(k.x,k.x, fmaf(k.y,k.y, fmaf(k.z,k.z, fmaf(k.w,k.w, kk))));
        aa = fmaf(a.x,a.x, fmaf(a.y,a.y, fmaf(a.z,a.z, fmaf(a.w,a.w, aa))));
        ka = fmaf(k.x,a.x, fmaf(k.y,a.y, fmaf(k.z,a.z, fmaf(k.w,a.w, ka))));
    }
    #pragma unroll
    for (int o = 16; o; o >>= 1) {
        kk += __shfl_xor_sync(0xffffffffu, kk, o);
        aa += __shfl_xor_sync(0xffffffffu, aa, o);
        ka += __shfl_xor_sync(0xffffffffu, ka, o);
    }
    if (ln == 0) {
        float ik = 1.f / fmaxf(sqrtf(kk), 1e-12f);
        float ia = 1.f / fmaxf(sqrtf(aa), 1e-12f);
        g_invK[gw] = ik;
        g_coef[gw] = ka * ik * ia;
    }
}

// =====================================================================
// Kernel B: scores GEMM (fp32) + top-5.  Block = (l, 32 batches), 128 thr.
// Double-buffered smem staging with register prefetch (R12 win).
// Lane 0 writes PACKED outputs: wq float4, aux uint2 {w4, idx0..3 bytes},
// i4 uint8 — matching out_kernel's 75 KB smem layout.
// =====================================================================
__global__ __launch_bounds__(128) void score_kernel(const float* __restrict__ x_query,
                                                    const float* __restrict__ K_all) {
    const int l  = blockIdx.y;
    const int b0 = blockIdx.x * BT;

    __shared__ __align__(16) float pool[2 * HALF];   // 39.2 KB

    const int t   = threadIdx.x;
    const int tx  = t & 15;          // p group
    const int ty  = t >> 4;          // 0..7 -> batches 4ty..4ty+3
    const int ldp = (t & 7) << 2;    // loader d offset 0..28
    const int lr  = t >> 3;          // loader row 0..15

    float acc[4][7];
    #pragma unroll
    for (int i = 0; i < 4; ++i)
        #pragma unroll
        for (int j = 0; j < 7; ++j) acc[i][j] = 0.f;

    const float* Kb = K_all   + (size_t)l * P_ * D_ + ldp;
    const float* xb = x_query + (size_t)l * D_ + ldp;

    float4 pk[7], px[2];
    #pragma unroll
    for (int j = 0; j < 7; ++j) {
        int p = lr + (j << 4);
        pk[j] = (p < P_) ? *(const float4*)(Kb + (size_t)p * D_)
                         : make_float4(0.f, 0.f, 0.f, 0.f);
    }
    #pragma unroll
    for (int i = 0; i < 2; ++i)
        px[i] = *(const float4*)(xb + (size_t)(b0 + lr + (i << 4)) * (L_ * D_));
    {
        float* Kc = pool;
        float* Xc = pool + PP * KPITCH;
        #pragma unroll
        for (int j = 0; j < 7; ++j) {
            float* r = &Kc[(lr + (j << 4)) * KPITCH + ldp];
            *(float2*)(r    ) = make_float2(pk[j].x, pk[j].y);
            *(float2*)(r + 2) = make_float2(pk[j].z, pk[j].w);
        }
        #pragma unroll
        for (int i = 0; i < 2; ++i) {
            float* r = &Xc[(lr + (i << 4)) * XPITCH + ldp];
            *(float2*)(r    ) = make_float2(px[i].x, px[i].y);
            *(float2*)(r + 2) = make_float2(px[i].z, px[i].w);
        }
    }
    __syncthreads();

    for (int c = 0; c < NCH; ++c) {
        const float* base = pool + (c & 1) * HALF;
        const float* Kc = base;
        const float* Xc = base + PP * KPITCH;

        if (c + 1 < NCH) {
            int d0 = (c + 1) * DC;
            #pragma unroll
            for (int j = 0; j < 7; ++j) {
                int p = lr + (j << 4);
                pk[j] = (p < P_) ? *(const float4*)(Kb + (size_t)p * D_ + d0)
                                 : make_float4(0.f, 0.f, 0.f, 0.f);
            }
            #pragma unroll
            for (int i = 0; i < 2; ++i)
                px[i] = *(const float4*)(xb + (size_t)(b0 + lr + (i << 4)) * (L_ * D_) + d0);
        }

        #pragma unroll 2
        for (int dd = 0; dd < DC; dd += 2) {
            float2 kv[7], xv[4];
            #pragma unroll
            for (int j = 0; j < 7; ++j) kv[j] = *(const float2*)&Kc[(tx + (j << 4)) * KPITCH + dd];
            #pragma unroll
            for (int i = 0; i < 4; ++i) xv[i] = *(const float2*)&Xc[(4 * ty + i) * XPITCH + dd];
            #pragma unroll
            for (int i = 0; i < 4; ++i)
                #pragma unroll
                for (int j = 0; j < 7; ++j) {
                    acc[i][j] = fmaf(xv[i].x, kv[j].x, acc[i][j]);
                    acc[i][j] = fmaf(xv[i].y, kv[j].y, acc[i][j]);
                }
        }

        if (c + 1 < NCH) {
            float* dst = pool + ((c + 1) & 1) * HALF;
            float* Kd = dst;
            float* Xd = dst + PP * KPITCH;
            #pragma unroll
            for (int j = 0; j < 7; ++j) {
                float* r = &Kd[(lr + (j << 4)) * KPITCH + ldp];
                *(float2*)(r    ) = make_float2(pk[j].x, pk[j].y);
                *(float2*)(r + 2) = make_float2(pk[j].z, pk[j].w);
            }
            #pragma unroll
            for (int i = 0; i < 2; ++i) {
                float* r = &Xd[(lr + (i << 4)) * XPITCH + ldp];
                *(float2*)(r    ) = make_float2(px[i].x, px[i].y);
                *(float2*)(r + 2) = make_float2(px[i].z, px[i].w);
            }
        }
        __syncthreads();
    }

    float* S = pool;   // [BT][128], aliases buffer 0

    #pragma unroll
    for (int j = 0; j < 8; ++j) {
        int p = tx + (j << 4);
        float ik = (p < P_) ? g_invK[l * P_ + p] : 0.f;
        #pragma unroll
        for (int i = 0; i < 4; ++i) {
            float v = (j < 7 && p < P_) ? acc[i][j] * ik : -FLT_MAX;
            S[(4 * ty + i) * 128 + p] = v;
        }
    }
    __syncthreads();

    const int w  = t >> 5;
    const int ln = t & 31;
    for (int bi = 0; bi < 8; ++bi) {
        int b = (w << 3) + bi;           // 0..31
        float v[4];
        #pragma unroll
        for (int j = 0; j < 4; ++j) v[j] = S[b * 128 + ln + (j << 5)];
        float wv[TOPK]; int iv[TOPK];
        #pragma unroll
        for (int k = 0; k < TOPK; ++k) {
            float bv = v[0]; int bj = 0;
            #pragma unroll
            for (int j = 1; j < 4; ++j) if (v[j] > bv) { bv = v[j]; bj = j; }
            int bidx = ln + (bj << 5);
            #pragma unroll
            for (int o = 16; o; o >>= 1) {
                float ov = __shfl_xor_sync(0xffffffffu, bv, o);
                int   oi = __shfl_xor_sync(0xffffffffu, bidx, o);
                if (ov > bv || (ov == bv && oi < bidx)) { bv = ov; bidx = oi; }
            }
            wv[k] = g_coef[l * P_ + bidx];   // only lane 0's value is used
            iv[k] = bidx;
            if ((bidx & 31) == ln) v[bidx >> 5] = -FLT_MAX;
        }
        if (ln == 0) {
            int gb = l * B_ + b0 + b;
            g_wq[gb] = make_float4(wv[0], wv[1], wv[2], wv[3]);
            unsigned int packed = (unsigned int)iv[0] | ((unsigned int)iv[1] << 8)
                                | ((unsigned int)iv[2] << 16) | ((unsigned int)iv[3] << 24);
            g_aux[gb] = make_uint2(__float_as_uint(wv[4]), packed);
            g_i4[gb]  = (unsigned char)iv[4];
        }
    }
}

// =====================================================================
// Kernel C: OUT[l,b,:] = sum_k w[l,b,k] * P_all[l, idx[l,b,k], :]
// Block = (l, coltile 128) serving ALL 1024 batches; P col-slice staged
// once per block.  R17: weights/indices smem-staged in PACKED form
// (idx as bytes) -> smem 92 KB -> 75 KB -> 3 blocks/SM = 48 warps
// (R15 was 2 blocks / 32 warps, occ 45%, L1=81%).
// =====================================================================
__global__ __launch_bounds__(OTHR, 3) void out_kernel(const float* __restrict__ P_all,
                                                      float* __restrict__ out) {
    extern __shared__ __align__(16) char smem[];
    float*  Ps  = (float*) (smem + SM_PS);    // [P_][CC]
    float4* wq  = (float4*)(smem + SM_WQ);    // [B_]
    uint2*  aux = (uint2*) (smem + SM_AUX);   // [B_]
    unsigned char* i4a = (unsigned char*)(smem + SM_I4);  // [B_]

    const int l    = blockIdx.y;
    const int col0 = blockIdx.x * CC;
    const int t    = threadIdx.x;

    // stage packed weights/indices (coalesced LDG)
    for (int i = t; i < B_; i += OTHR) {
        int gb = l * B_ + i;
        wq[i]  = g_wq[gb];
        aux[i] = g_aux[gb];
        i4a[i] = g_i4[gb];
    }
    // stage P col-slice once: 100 rows x 128 cols (float4 loads/stores)
    const float* Pl = P_all + (size_t)l * P_ * ROW_ + col0;
    for (int i = t; i < P_ * (CC / 4); i += OTHR) {
        int p = i >> 5, c = i & 31;              // 32 float4 per row
        float4 v = *(const float4*)(Pl + (size_t)p * ROW_ + 4 * c);
        *(float4*)&Ps[p * CC + 4 * c] = v;
    }
    __syncthreads();

    const int w  = t >> 5;                       // 0..15
    const int ln = t & 31;
    float* ob = out + (size_t)l * B_ * ROW_ + col0 + 4 * ln;
    for (int b = w; b < B_; b += OTHR / 32) {
        float4 wv = wq[b];                       // LDS.128 broadcast
        uint2  ax = aux[b];                      // LDS.64 broadcast
        float  w4 = __uint_as_float(ax.x);
        unsigned int ip = ax.y;
        int    i0 = ip & 0xFF, i1 = (ip >> 8) & 0xFF,
               i2 = (ip >> 16) & 0xFF, i3 = ip >> 24;
        int    i4 = i4a[b];                      // LDS.U8 broadcast
        float4 p0 = *(const float4*)&Ps[i0 * CC + 4 * ln];
        float4 p1 = *(const float4*)&Ps[i1 * CC + 4 * ln];
        float4 p2 = *(const float4*)&Ps[i2 * CC + 4 * ln];
        float4 p3 = *(const float4*)&Ps[i3 * CC + 4 * ln];
        float4 p4 = *(const float4*)&Ps[i4 * CC + 4 * ln];
        float4 o;
        o.x = fmaf(w4, p4.x, fmaf(wv.w, p3.x, fmaf(wv.z, p2.x, fmaf(wv.y, p1.x, wv.x * p0.x))));
        o.y = fmaf(w4, p4.y, fmaf(wv.w, p3.y, fmaf(wv.z, p2.y, fmaf(wv.y, p1.y, wv.x * p0.y))));
        o.z = fmaf(w4, p4.z, fmaf(wv.w, p3.z, fmaf(wv.z, p2.z, fmaf(wv.y, p1.z, wv.x * p0.z))));
        o.w = fmaf(w4, p4.w, fmaf(wv.w, p3.w, fmaf(wv.z, p2.w, fmaf(wv.y, p1.w, wv.x * p0.w))));
        *(float4*)(ob + (size_t)b * ROW_) = o;
    }
}

// =====================================================================
// Dummy launch at position 3: ncu captures launch position 4 (confirmed
// R9/R11-R16).  Order prep, score, phase, out -> profile lands on the
// NEW out_kernel (verify occupancy theory).
// =====================================================================
__global__ void phase_kernel() { g_sink = 1; }

// =====================================================================
extern "C" void kernel_launch(void* const* d_in, const int* in_sizes, int n_in,
                              void* d_out, int out_size) {
    const float* x_query = (const float*)d_in[0];  // [B, L, D]
    const float* K_all   = (const float*)d_in[1];  // [L, P, D]
    const float* A_all   = (const float*)d_in[2];  // [L, P, D]
    const float* P_all   = (const float*)d_in[3];  // [L, P, Lp, D]
    float* out = (float*)d_out;                    // [L, B, Lp, E]
    (void)in_sizes; (void)n_in; (void)out_size;

    cudaFuncSetAttribute(out_kernel, cudaFuncAttributeMaxDynamicSharedMemorySize, SMEM_OUT);

    prep_kernel<<<(L_ * P_ * 32 + 255) / 256, 256>>>(K_all, A_all);
    score_kernel<<<dim3(B_ / BT, L_), 128>>>(x_query, K_all);
    phase_kernel<<<1, 1>>>();
    out_kernel<<<dim3(ROW_ / CC, L_), OTHR, SMEM_OUT>>>(P_all, out);
}